// round 14
// baseline (speedup 1.0000x reference)
#include <cuda_runtime.h>
#include <cuda_fp16.h>
#include <cstdint>

#define B_   4
#define V_   256
#define H_   128
#define KE_  32
#define H2_  256
#define ST_W 136
#define ST_E2 40
#define NBI  (B_*V_)
#define ETILE 10240          // shorts per bi (256 rows)
#define ECHUNK_SH 5120       // shorts per chunk (128 rows)
#define ECHUNK_B 10240       // bytes per chunk

__device__ float g_P [NBI*H_];
__device__ float g_Q [NBI*H_];
__device__ float g_X1[NBI*H_];
__device__ float g_X2[NBI*H_];
__device__ float g_R [NBI*H2_];
__device__ float g_S [NBI*H2_];
__device__ __align__(16) unsigned short g_w1hi[2][KE_*ST_W];
__device__ __align__(16) unsigned short g_w2hi[2][H_*ST_W];
__device__ __align__(16) unsigned short g_Ehi[NBI][ETILE];

__device__ __forceinline__ unsigned short f16b(float f) {
    __half h = __float2half_rn(f);
    return *(unsigned short*)&h;
}
__device__ __forceinline__ uint32_t smem_to_u32(const void* p) {
    uint32_t a;
    asm("{ .reg .u64 t; cvta.to.shared.u64 t, %1; cvt.u32.u64 %0, t; }" : "=r"(a) : "l"(p));
    return a;
}
__device__ __forceinline__ void ldsm4(uint32_t* r, uint32_t a) {
    asm volatile("ldmatrix.sync.aligned.m8n8.x4.shared.b16 {%0,%1,%2,%3}, [%4];"
        : "=r"(r[0]), "=r"(r[1]), "=r"(r[2]), "=r"(r[3]) : "r"(a));
}
__device__ __forceinline__ void ldsm4t(uint32_t* r, uint32_t a) {
    asm volatile("ldmatrix.sync.aligned.m8n8.x4.trans.shared.b16 {%0,%1,%2,%3}, [%4];"
        : "=r"(r[0]), "=r"(r[1]), "=r"(r[2]), "=r"(r[3]) : "r"(a));
}
__device__ __forceinline__ void mma_f16(float* c, const uint32_t* a, const uint32_t* b) {
    asm volatile("mma.sync.aligned.m16n8k16.row.col.f32.f16.f16.f32 "
        "{%0,%1,%2,%3}, {%4,%5,%6,%7}, {%8,%9}, {%0,%1,%2,%3};"
        : "+f"(c[0]), "+f"(c[1]), "+f"(c[2]), "+f"(c[3])
        : "r"(a[0]), "r"(a[1]), "r"(a[2]), "r"(a[3]), "r"(b[0]), "r"(b[1]));
}
__device__ __forceinline__ void cp16(uint32_t dst, const void* src) {
    asm volatile("cp.async.cg.shared.global [%0], [%1], 16;" :: "r"(dst), "l"(src));
}
#define CP_COMMIT() asm volatile("cp.async.commit_group;" ::: "memory")
#define CP_WAIT1()  asm volatile("cp.async.wait_group 1;" ::: "memory")
#define CP_WAIT0()  asm volatile("cp.async.wait_group 0;" ::: "memory")

// SMEM byte offsets (ec kernel, j-split: one chunk per CTA)
#define OFF_B2    0
#define OFF_P     512
#define OFF_ADJ   1024
#define OFF_RED   1536
#define OFF_W1HI  5632
#define OFF_W2HI  14336
#define OFF_E0    49152
#define SMEM_EC   (OFF_E0 + 2*ECHUNK_B)   // 69632

// ---------------------------------------------------------------------------
__device__ __forceinline__ void pq_impl(int group, const float* __restrict__ x,
                                        const float* __restrict__ W1,
                                        const float* __restrict__ b1, int C_in,
                                        float* __restrict__ P, float* __restrict__ Q)
{
    __shared__ float sx[4][128];
    __shared__ float sp[2][4][128], sq[2][4][128];
    const int tid = threadIdx.x;
    const int cs = tid >> 7, h = tid & 127;
    const int base = group * 4;
    const int lg = (C_in == 64) ? 6 : 7;
    for (int i = tid; i < 4*C_in; i += 256)
        sx[i >> lg][i & (C_in-1)] = x[(size_t)(base + (i >> lg))*C_in + (i & (C_in-1))];
    __syncthreads();

    const int c0 = cs * (C_in >> 1), c1 = c0 + (C_in >> 1);
    float p[4] = {0.f,0.f,0.f,0.f}, q[4] = {0.f,0.f,0.f,0.f};
    for (int c = c0; c < c1; ++c) {
        float wa = W1[c*H_ + h], wb = W1[(C_in+c)*H_ + h], wd = wa - wb;
        #pragma unroll
        for (int r = 0; r < 4; ++r) { p[r] += sx[r][c]*wd; q[r] += sx[r][c]*wb; }
    }
    #pragma unroll
    for (int r = 0; r < 4; ++r) { sp[cs][r][h] = p[r]; sq[cs][r][h] = q[r]; }
    __syncthreads();
    if (cs == 0) {
        float bb = b1[h];
        #pragma unroll
        for (int r = 0; r < 4; ++r) {
            P[(size_t)(base+r)*H_ + h] = sp[0][r][h] + sp[1][r][h] + bb;
            Q[(size_t)(base+r)*H_ + h] = sq[0][r][h] + sq[1][r][h];
        }
    }
}

// Merged prep: E-convert + ZERO X1/X2 + weight prep + pq layer 1.
__global__ void prep_all(const float* __restrict__ E,
                         const float* __restrict__ W1a, const float* __restrict__ W2a,
                         const float* __restrict__ W1b, const float* __restrict__ W2b,
                         const float* __restrict__ x0,  const float* __restrict__ b1a,
                         float* __restrict__ P, float* __restrict__ Q,
                         float* __restrict__ X1, float* __restrict__ X2)
{
    const int blk = blockIdx.x, tid = threadIdx.x;
    if (blk < NBI) {
        unsigned short* eh = g_Ehi[blk];
        for (int idx = tid; idx < 2048; idx += 256) {
            int j = idx >> 3, kq = idx & 7;
            float4 e4 = *(const float4*)(E + ((size_t)blk*V_ + j)*KE_ + kq*4);
            uint2 hp;
            hp.x = (uint32_t)f16b(e4.x) | ((uint32_t)f16b(e4.y) << 16);
            hp.y = (uint32_t)f16b(e4.z) | ((uint32_t)f16b(e4.w) << 16);
            *(uint2*)(eh + j*ST_E2 + kq*4) = hp;
        }
        if (tid < H_) {               // zero accumulate targets (replay-safe)
            X1[(size_t)blk*H_ + tid] = 0.f;
            X2[(size_t)blk*H_ + tid] = 0.f;
        }
    } else if (blk < NBI + 160) {
        int idx = (blk - NBI) * 256 + tid;
        if (idx < 40960) {
            int layer = idx / 20480;
            int t = idx - layer * 20480;
            const float* W1 = layer ? W1b : W1a;
            const float* W2 = layer ? W2b : W2a;
            const int C = layer ? 128 : 64;
            if (t < KE_*H_) {
                int k = t >> 7, c = t & 127;
                g_w1hi[layer][k*ST_W + c] = f16b(W1[(size_t)(2*C + k)*H_ + c]);
            } else {
                int t2 = t - KE_*H_;
                int k = t2 >> 7, c = t2 & 127;
                g_w2hi[layer][k*ST_W + c] = f16b(W2[(size_t)k*H_ + c]);
            }
        }
    } else {
        pq_impl(blk - (NBI + 160), x0, W1a, b1a, 64, P, Q);
    }
}

__global__ void pq_kernel(const float* __restrict__ x, const float* __restrict__ W1,
                          const float* __restrict__ b1, int C_in,
                          float* __restrict__ P, float* __restrict__ Q)
{
    pq_impl(blockIdx.x, x, W1, b1, C_in, P, Q);
}

// ---------------------------------------------------------------------------
// Persistent fused EdgeConv, single-fp16 HMMA, j-SPLIT: one CTA per
// (bi, chunk); cross-chunk max combined via atomicMax (values >= 0, exact).
// Register budget fits 2 CTAs/SM: phase 1 and phase 2 each run in n-halves.
// ---------------------------------------------------------------------------
__global__ void __launch_bounds__(256, 2)
ec_hmma(const float* __restrict__ Pg, const float* __restrict__ Qg,
        const float* __restrict__ b2, const int* __restrict__ adj,
        float* __restrict__ Xout, int layer)
{
    extern __shared__ char smem[];
    const uint32_t sb = smem_to_u32(smem);
    const int tid = threadIdx.x, w = tid >> 5, lane = tid & 31;
    const int g = lane >> 2, tg = lane & 3;
    const int j0 = w * 16;
    const int rowsel = lane & 15, colsel = (lane >> 4) * 8;
    const int NT = 2 * NBI;

    {   // stage weight tiles ONCE per CTA
        const uint4* s; uint4* d;
        s = (const uint4*)g_w1hi[layer]; d = (uint4*)(smem + OFF_W1HI);
        for (int i = tid; i < 544;  i += 256) d[i] = s[i];
        s = (const uint4*)g_w2hi[layer]; d = (uint4*)(smem + OFF_W2HI);
        for (int i = tid; i < 2176; i += 256) d[i] = s[i];
    }
    float* sPf  = (float*)(smem + OFF_P);
    float* sB2f = (float*)(smem + OFF_B2);
    int*   sAdj = (int*)(smem + OFF_ADJ);
    float* red  = (float*)(smem + OFF_RED);
    if (tid < H_) sB2f[tid] = b2[tid];

    int cur = 0;
    {   // prefetch first task's E chunk
        const int bi0 = blockIdx.x & (NBI-1), ch0 = blockIdx.x >> 10;
        const char* sh = (const char*)(g_Ehi[bi0] + ch0*ECHUNK_SH);
        for (int i = tid; i < ECHUNK_B/16; i += 256)
            cp16(sb + OFF_E0 + i*16, sh + i*16);
        CP_COMMIT();
    }

    for (int task = blockIdx.x; task < NT; task += gridDim.x) {
        const int bi = task & (NBI-1);
        const int ch = task >> 10;
        const int b  = bi >> 8;
        const int jbase = ch * 128;

        float pv = (tid < H_) ? Pg[(size_t)bi*H_ + tid] : 0.f;
        int   av = (tid < H_) ? adj[(size_t)bi*V_ + jbase + tid] : 0;

        const int ntask = task + gridDim.x;
        if (ntask < NT) {
            const int nb = 1 - cur;
            const int bi2 = ntask & (NBI-1), ch2 = ntask >> 10;
            const char* sh = (const char*)(g_Ehi[bi2] + ch2*ECHUNK_SH);
            for (int i = tid; i < ECHUNK_B/16; i += 256)
                cp16(sb + OFF_E0 + nb*ECHUNK_B + i*16, sh + i*16);
            CP_COMMIT();
            CP_WAIT1();
        } else {
            CP_WAIT0();
        }
        if (tid < H_) { sPf[tid] = pv; sAdj[tid] = av; }
        #pragma unroll
        for (int i = 0; i < 4; ++i) red[w*H_ + lane*4 + i] = -1e9f;
        __syncthreads();

        const uint32_t eH = sb + OFF_E0 + cur*ECHUNK_B;

        // ---- phase 1 (E @ W1c, K=32) in 2 n-halves -> aH2[8][4] ----
        uint32_t aH2[8][4];
        #pragma unroll
        for (int h1 = 0; h1 < 2; ++h1) {
            float acc[8][4];
            #pragma unroll
            for (int n = 0; n < 8; ++n)
                #pragma unroll
                for (int p = 0; p < 4; ++p) acc[n][p] = 0.f;

            #pragma unroll
            for (int ks = 0; ks < 2; ++ks) {
                uint32_t aH[4];
                uint32_t ao = (uint32_t)((j0 + rowsel)*ST_E2 + ks*16 + colsel) * 2u;
                ldsm4(aH, eH + ao);
                const uint32_t brow = (uint32_t)((ks*16 + rowsel)*ST_W + colsel) * 2u;
                #pragma unroll
                for (int ntp = 0; ntp < 4; ++ntp) {
                    uint32_t bH[4];
                    ldsm4t(bH, sb + OFF_W1HI + brow + (uint32_t)((h1*4 + ntp)*32));
                    mma_f16(acc[2*ntp],   aH, &bH[0]);
                    mma_f16(acc[2*ntp+1], aH, &bH[2]);
                }
            }

            // epilogue 1 (this half): T = relu(P + Q + D) -> aH2[4h1..4h1+3]
            const float* qA = Qg + ((size_t)(b*V_ + jbase + j0 + g))*H_;
            const float* qB = qA + 8*H_;
            #pragma unroll
            for (int ks2 = 0; ks2 < 4; ++ks2) {
                const int ksg = 4*h1 + ks2;
                #pragma unroll
                for (int h = 0; h < 2; ++h) {
                    const int ntl = 2*ks2 + h;
                    const int c = (2*ksg + h)*8 + tg*2;
                    float2 q0 = *(const float2*)(qA + c);
                    float2 q1 = *(const float2*)(qB + c);
                    float pc0 = sPf[c], pc1 = sPf[c+1];
                    float t0 = fmaxf(acc[ntl][0] + pc0 + q0.x, 0.f);
                    float t1 = fmaxf(acc[ntl][1] + pc1 + q0.y, 0.f);
                    float t2 = fmaxf(acc[ntl][2] + pc0 + q1.x, 0.f);
                    float t3 = fmaxf(acc[ntl][3] + pc1 + q1.y, 0.f);
                    aH2[ksg][0 + 2*h] = (uint32_t)f16b(t0) | ((uint32_t)f16b(t1) << 16);
                    aH2[ksg][1 + 2*h] = (uint32_t)f16b(t2) | ((uint32_t)f16b(t3) << 16);
                }
            }
        }

        const bool actA = sAdj[j0 + g] > 0, actB = sAdj[j0 + 8 + g] > 0;

        // ---- phase 2 (T @ W2, K=128) in 2 n-halves ----
        #pragma unroll
        for (int half = 0; half < 2; ++half) {
            float a0[8][4];
            #pragma unroll
            for (int n = 0; n < 8; ++n)
                #pragma unroll
                for (int p = 0; p < 4; ++p) a0[n][p] = 0.f;

            #pragma unroll
            for (int ks = 0; ks < 8; ++ks) {
                const uint32_t brow =
                    (uint32_t)((ks*16 + rowsel)*ST_W + half*64 + colsel) * 2u;
                #pragma unroll
                for (int ntp = 0; ntp < 4; ++ntp) {
                    uint32_t bH[4];
                    ldsm4t(bH, sb + OFF_W2HI + brow + (uint32_t)(ntp*32));
                    mma_f16(a0[2*ntp],   aH2[ks], &bH[0]);
                    mma_f16(a0[2*ntp+1], aH2[ks], &bH[2]);
                }
            }

            // epilogue 2 (this half): relu(+b2), masked max -> red
            #pragma unroll
            for (int nt = 0; nt < 8; ++nt) {
                const int gnt = half*8 + nt;
                const int c = gnt*8 + tg*2;
                float b0 = sB2f[c], b1 = sB2f[c+1];
                float r0 = -1e9f, r1 = -1e9f;
                if (actA) {
                    r0 = fmaxf(r0, fmaxf(a0[nt][0]+b0, 0.f));
                    r1 = fmaxf(r1, fmaxf(a0[nt][1]+b1, 0.f));
                }
                if (actB) {
                    r0 = fmaxf(r0, fmaxf(a0[nt][2]+b0, 0.f));
                    r1 = fmaxf(r1, fmaxf(a0[nt][3]+b1, 0.f));
                }
                #pragma unroll
                for (int off = 4; off <= 16; off <<= 1) {
                    r0 = fmaxf(r0, __shfl_xor_sync(0xffffffffu, r0, off));
                    r1 = fmaxf(r1, __shfl_xor_sync(0xffffffffu, r1, off));
                }
                if (lane < 4) {
                    int ci = w*H_ + gnt*8 + lane*2;
                    red[ci]   = fmaxf(red[ci],   r0);
                    red[ci+1] = fmaxf(red[ci+1], r1);
                }
            }
        }

        __syncthreads();
        if (tid < H_) {
            float v = red[tid];
            #pragma unroll
            for (int ww = 1; ww < 8; ++ww) v = fmaxf(v, red[ww*H_ + tid]);
            // relu values >= 0; zero-init + atomicMax(int view) is exact and
            // reproduces the "all-masked -> 0" semantics.
            atomicMax((int*)(Xout + (size_t)bi*H_ + tid),
                      __float_as_int(fmaxf(v, 0.f)));
        }
        __syncthreads();
        cur ^= 1;
    }
}

// ---------------------------------------------------------------------------
__global__ void __launch_bounds__(512)
rs_kernel(const float* __restrict__ x, const float* __restrict__ W3,
          const float* __restrict__ b3,
          float* __restrict__ R, float* __restrict__ S)
{
    __shared__ float sx[4][128];
    __shared__ float sr[2][4][256], ss[2][4][256];
    const int tid = threadIdx.x;
    const int cs = tid >> 8, m = tid & 255;
    const int base = blockIdx.x * 4;
    sx[tid >> 7][tid & 127] = x[(size_t)(base + (tid >> 7))*H_ + (tid & 127)];
    __syncthreads();

    const int c0 = cs * 64, c1 = c0 + 64;
    float r[4] = {0.f,0.f,0.f,0.f}, s[4] = {0.f,0.f,0.f,0.f};
    for (int c = c0; c < c1; ++c) {
        float wa = W3[c*H2_ + m], wb = W3[(128+c)*H2_ + m];
        #pragma unroll
        for (int rr = 0; rr < 4; ++rr) { r[rr] += sx[rr][c]*wa; s[rr] += sx[rr][c]*wb; }
    }
    #pragma unroll
    for (int rr = 0; rr < 4; ++rr) { sr[cs][rr][m] = r[rr]; ss[cs][rr][m] = s[rr]; }
    __syncthreads();
    if (cs == 0) {
        float bb = b3[m];
        #pragma unroll
        for (int rr = 0; rr < 4; ++rr) {
            R[(size_t)(base+rr)*H2_ + m] = sr[0][rr][m] + sr[1][rr][m];
            S[(size_t)(base+rr)*H2_ + m] = ss[0][rr][m] + ss[1][rr][m] + bb;
        }
    }
}

#define IL_ 8
#define MC_ 32
__global__ void __launch_bounds__(256)
pair_kernel(const float* __restrict__ R, const float* __restrict__ S,
            const float* __restrict__ outW, const float* __restrict__ outB,
            float* __restrict__ out)
{
    __shared__ float sR[V_][MC_+1];
    __shared__ float sS[IL_][MC_+1];
    __shared__ float sw[MC_];
    const int tid = threadIdx.x;
    const int b = blockIdx.y, i0 = blockIdx.x * IL_;
    float acc[IL_];
    #pragma unroll
    for (int il = 0; il < IL_; ++il) acc[il] = 0.f;

    for (int mc = 0; mc < H2_; mc += MC_) {
        __syncthreads();
        #pragma unroll 4
        for (int idx = tid; idx < V_*MC_; idx += 256) {
            int j = idx >> 5, mm = idx & (MC_-1);
            sR[j][mm] = R[((size_t)b*V_ + j)*H2_ + mc + mm];
        }
        if (tid < IL_*MC_) {
            int il = tid >> 5, mm = tid & (MC_-1);
            sS[il][mm] = S[((size_t)b*V_ + i0 + il)*H2_ + mc + mm];
        }
        if (tid < MC_) sw[tid] = outW[mc + tid];
        __syncthreads();
        #pragma unroll
        for (int il = 0; il < IL_; ++il) {
            float a = 0.f;
            #pragma unroll
            for (int mm = 0; mm < MC_; ++mm)
                a += fmaxf(sR[tid][mm] + sS[il][mm], 0.f) * sw[mm];
            acc[il] += a;
        }
    }
    const float ob = outB[0];
    #pragma unroll
    for (int il = 0; il < IL_; ++il) {
        float z = acc[il] + ob;
        out[((size_t)b*V_ + i0 + il)*V_ + tid] = 1.f / (1.f + expf(-z));
    }
}

// ---------------------------------------------------------------------------
extern "C" void kernel_launch(void* const* d_in, const int* in_sizes, int n_in,
                              void* d_out, int out_size)
{
    const int*   adj   = (const int*)  d_in[0];
    const float* x0    = (const float*)d_in[1];
    const float* e     = (const float*)d_in[2];
    const float* ec1W1 = (const float*)d_in[3];
    const float* ec1b1 = (const float*)d_in[4];
    const float* ec1W2 = (const float*)d_in[5];
    const float* ec1b2 = (const float*)d_in[6];
    const float* ec2W1 = (const float*)d_in[7];
    const float* ec2b1 = (const float*)d_in[8];
    const float* ec2W2 = (const float*)d_in[9];
    const float* ec2b2 = (const float*)d_in[10];
    const float* h3W   = (const float*)d_in[11];
    const float* h3b   = (const float*)d_in[12];
    const float* outW  = (const float*)d_in[13];
    const float* outB  = (const float*)d_in[14];
    float* out = (float*)d_out;

    float *P, *Q, *X1, *X2, *R, *S;
    cudaGetSymbolAddress((void**)&P,  g_P);
    cudaGetSymbolAddress((void**)&Q,  g_Q);
    cudaGetSymbolAddress((void**)&X1, g_X1);
    cudaGetSymbolAddress((void**)&X2, g_X2);
    cudaGetSymbolAddress((void**)&R,  g_R);
    cudaGetSymbolAddress((void**)&S,  g_S);

    cudaFuncSetAttribute(ec_hmma, cudaFuncAttributeMaxDynamicSharedMemorySize, SMEM_EC);

    int sms = 148;
    cudaDeviceGetAttribute(&sms, cudaDevAttrMultiProcessorCount, 0);
    int grid = 2 * sms;
    if (grid > 2*NBI) grid = 2*NBI;

    prep_all<<<NBI + 160 + 256, 256>>>(e, ec1W1, ec1W2, ec2W1, ec2W2,
                                       x0, ec1b1, P, Q, X1, X2);

    ec_hmma<<<grid, 256, SMEM_EC>>>(P, Q, ec1b2, adj, X1, 0);

    pq_kernel<<<NBI/4, 256>>>(X1, ec2W1, ec2b1, 128, P, Q);
    ec_hmma<<<grid, 256, SMEM_EC>>>(P, Q, ec2b2, adj, X2, 1);

    rs_kernel<<<NBI/4, 512>>>(X2, h3W, h3b, R, S);
    dim3 pg(V_/IL_, B_);
    pair_kernel<<<pg, 256>>>(R, S, outW, outB, out);
}

// round 15
// speedup vs baseline: 1.0728x; 1.0728x over previous
#include <cuda_runtime.h>
#include <cuda_fp16.h>
#include <cstdint>

#define B_   4
#define V_   256
#define H_   128
#define KE_  32
#define H2_  256
#define ST_W 136
#define ST_E2 40
#define NBI  (B_*V_)
#define ETILE 10240
#define EBYTES 20480

__device__ float g_P [NBI*H_];
__device__ float g_Q [NBI*H_];
__device__ float g_P2[NBI*H_];
__device__ float g_Q2[NBI*H_];
__device__ float g_R [NBI*H2_];
__device__ float g_S [NBI*H2_];
__device__ __align__(16) unsigned short g_w1hi[2][KE_*ST_W];
__device__ __align__(16) unsigned short g_w2hi[2][H_*ST_W];
__device__ __align__(16) unsigned short g_Ehi[NBI][ETILE];
// fp16 tail-weight tiles (for fused pq / rs epilogues)
__device__ __align__(16) unsigned short g_tw0d[128*128];   // W1(ec2) a-b diff
__device__ __align__(16) unsigned short g_tw0b[128*128];   // W1(ec2) b part
__device__ __align__(16) unsigned short g_tw1a[128*256];   // h3W rows 0..127
__device__ __align__(16) unsigned short g_tw1b[128*256];   // h3W rows 128..255

__device__ __forceinline__ unsigned short f16b(float f) {
    __half h = __float2half_rn(f);
    return *(unsigned short*)&h;
}
__device__ __forceinline__ uint32_t smem_to_u32(const void* p) {
    uint32_t a;
    asm("{ .reg .u64 t; cvta.to.shared.u64 t, %1; cvt.u32.u64 %0, t; }" : "=r"(a) : "l"(p));
    return a;
}
__device__ __forceinline__ void ldsm4(uint32_t* r, uint32_t a) {
    asm volatile("ldmatrix.sync.aligned.m8n8.x4.shared.b16 {%0,%1,%2,%3}, [%4];"
        : "=r"(r[0]), "=r"(r[1]), "=r"(r[2]), "=r"(r[3]) : "r"(a));
}
__device__ __forceinline__ void ldsm4t(uint32_t* r, uint32_t a) {
    asm volatile("ldmatrix.sync.aligned.m8n8.x4.trans.shared.b16 {%0,%1,%2,%3}, [%4];"
        : "=r"(r[0]), "=r"(r[1]), "=r"(r[2]), "=r"(r[3]) : "r"(a));
}
__device__ __forceinline__ void mma_f16(float* c, const uint32_t* a, const uint32_t* b) {
    asm volatile("mma.sync.aligned.m16n8k16.row.col.f32.f16.f16.f32 "
        "{%0,%1,%2,%3}, {%4,%5,%6,%7}, {%8,%9}, {%0,%1,%2,%3};"
        : "+f"(c[0]), "+f"(c[1]), "+f"(c[2]), "+f"(c[3])
        : "r"(a[0]), "r"(a[1]), "r"(a[2]), "r"(a[3]), "r"(b[0]), "r"(b[1]));
}
__device__ __forceinline__ void cp16(uint32_t dst, const void* src) {
    asm volatile("cp.async.cg.shared.global [%0], [%1], 16;" :: "r"(dst), "l"(src));
}
#define CP_COMMIT() asm volatile("cp.async.commit_group;" ::: "memory")
#define CP_WAIT1()  asm volatile("cp.async.wait_group 1;" ::: "memory")
#define CP_WAIT0()  asm volatile("cp.async.wait_group 0;" ::: "memory")

// SMEM byte offsets (ec kernel, R12 layout + tail-weight region)
#define OFF_B2    0
#define OFF_P     512
#define OFF_ADJ   1024
#define OFF_RED   2048
#define OFF_W1HI  6144
#define OFF_W2HI  14848
#define OFF_E0    49664
#define OFF_TW    (OFF_E0 + 2*EBYTES)          // 90624
#define SMEM_EC0  (OFF_TW + 2*32768)           // 156160 (layer 0)
#define SMEM_EC1  (OFF_TW + 2*65536)           // 221696 (layer 1)

// ---------------------------------------------------------------------------
__device__ __forceinline__ void pq_impl(int group, const float* __restrict__ x,
                                        const float* __restrict__ W1,
                                        const float* __restrict__ b1, int C_in,
                                        float* __restrict__ P, float* __restrict__ Q)
{
    __shared__ float sx[4][128];
    __shared__ float sp[2][4][128], sq[2][4][128];
    const int tid = threadIdx.x;
    const int cs = tid >> 7, h = tid & 127;
    const int base = group * 4;
    const int lg = (C_in == 64) ? 6 : 7;
    for (int i = tid; i < 4*C_in; i += 256)
        sx[i >> lg][i & (C_in-1)] = x[(size_t)(base + (i >> lg))*C_in + (i & (C_in-1))];
    __syncthreads();

    const int c0 = cs * (C_in >> 1), c1 = c0 + (C_in >> 1);
    float p[4] = {0.f,0.f,0.f,0.f}, q[4] = {0.f,0.f,0.f,0.f};
    for (int c = c0; c < c1; ++c) {
        float wa = W1[c*H_ + h], wb = W1[(C_in+c)*H_ + h], wd = wa - wb;
        #pragma unroll
        for (int r = 0; r < 4; ++r) { p[r] += sx[r][c]*wd; q[r] += sx[r][c]*wb; }
    }
    #pragma unroll
    for (int r = 0; r < 4; ++r) { sp[cs][r][h] = p[r]; sq[cs][r][h] = q[r]; }
    __syncthreads();
    if (cs == 0) {
        float bb = b1[h];
        #pragma unroll
        for (int r = 0; r < 4; ++r) {
            P[(size_t)(base+r)*H_ + h] = sp[0][r][h] + sp[1][r][h] + bb;
            Q[(size_t)(base+r)*H_ + h] = sq[0][r][h] + sq[1][r][h];
        }
    }
}

// Merged prep: E-convert + mainloop weights + tail weights + pq layer 1.
__global__ void prep_all(const float* __restrict__ E,
                         const float* __restrict__ W1a, const float* __restrict__ W2a,
                         const float* __restrict__ W1b, const float* __restrict__ W2b,
                         const float* __restrict__ h3W,
                         const float* __restrict__ x0,  const float* __restrict__ b1a,
                         float* __restrict__ P, float* __restrict__ Q)
{
    const int blk = blockIdx.x, tid = threadIdx.x;
    if (blk < NBI) {
        unsigned short* eh = g_Ehi[blk];
        for (int idx = tid; idx < 2048; idx += 256) {
            int j = idx >> 3, kq = idx & 7;
            float4 e4 = *(const float4*)(E + ((size_t)blk*V_ + j)*KE_ + kq*4);
            uint2 hp;
            hp.x = (uint32_t)f16b(e4.x) | ((uint32_t)f16b(e4.y) << 16);
            hp.y = (uint32_t)f16b(e4.z) | ((uint32_t)f16b(e4.w) << 16);
            *(uint2*)(eh + j*ST_E2 + kq*4) = hp;
        }
    } else if (blk < NBI + 160) {
        int idx = (blk - NBI) * 256 + tid;
        if (idx < 40960) {
            int layer = idx / 20480;
            int t = idx - layer * 20480;
            const float* W1 = layer ? W1b : W1a;
            const float* W2 = layer ? W2b : W2a;
            const int C = layer ? 128 : 64;
            if (t < KE_*H_) {
                int k = t >> 7, c = t & 127;
                g_w1hi[layer][k*ST_W + c] = f16b(W1[(size_t)(2*C + k)*H_ + c]);
            } else {
                int t2 = t - KE_*H_;
                int k = t2 >> 7, c = t2 & 127;
                g_w2hi[layer][k*ST_W + c] = f16b(W2[(size_t)k*H_ + c]);
            }
        }
    } else if (blk < NBI + 160 + 64) {
        // tail weights for fused pq (layer-2 W1: C_in = 128)
        int idx = (blk - (NBI + 160)) * 256 + tid;   // < 16384
        int c = idx >> 7, h = idx & 127;
        float wa = W1b[(size_t)c*H_ + h];
        float wb = W1b[(size_t)(128 + c)*H_ + h];
        g_tw0d[idx] = f16b(wa - wb);
        g_tw0b[idx] = f16b(wb);
    } else if (blk < NBI + 160 + 64 + 128) {
        // tail weights for fused rs (h3W)
        int idx = (blk - (NBI + 160 + 64)) * 256 + tid;  // < 32768
        int c = idx >> 8, m = idx & 255;
        g_tw1a[idx] = f16b(h3W[(size_t)c*H2_ + m]);
        g_tw1b[idx] = f16b(h3W[(size_t)(128 + c)*H2_ + m]);
    } else {
        pq_impl(blk - (NBI + 352), x0, W1a, b1a, 64, P, Q);
    }
}

// ---------------------------------------------------------------------------
// Persistent-CTA fused EdgeConv (R12 mainloop) + fused tail:
//  layer 0: compute P2/Q2 for layer 2 from the fresh X row (fp16 smem weights)
//  layer 1: compute R/S for the pair MLP from the fresh X row
// ---------------------------------------------------------------------------
__global__ void __launch_bounds__(256, 1)
ec_hmma(const float* __restrict__ Pg, const float* __restrict__ Qg,
        const float* __restrict__ b2, const int* __restrict__ adj,
        const float* __restrict__ bn,
        float* __restrict__ O1, float* __restrict__ O2, int layer)
{
    extern __shared__ char smem[];
    const uint32_t sb = smem_to_u32(smem);
    const int tid = threadIdx.x, w = tid >> 5, lane = tid & 31;
    const int g = lane >> 2, tg = lane & 3;
    const int j0 = w * 16;
    const int rowsel = lane & 15, colsel = (lane >> 4) * 8;

    {   // stage mainloop weight tiles + tail weight tiles ONCE
        const uint4* s; uint4* d;
        s = (const uint4*)g_w1hi[layer]; d = (uint4*)(smem + OFF_W1HI);
        for (int i = tid; i < 544;  i += 256) d[i] = s[i];
        s = (const uint4*)g_w2hi[layer]; d = (uint4*)(smem + OFF_W2HI);
        for (int i = tid; i < 2176; i += 256) d[i] = s[i];
        const int twb = (layer == 0) ? 32768 : 65536;
        const uint4* sa = (layer == 0) ? (const uint4*)g_tw0d : (const uint4*)g_tw1a;
        const uint4* sbp = (layer == 0) ? (const uint4*)g_tw0b : (const uint4*)g_tw1b;
        uint4* da = (uint4*)(smem + OFF_TW);
        uint4* db = (uint4*)(smem + OFF_TW + twb);
        for (int i = tid; i < twb/16; i += 256) { da[i] = sa[i]; db[i] = sbp[i]; }
    }
    float* sPf  = (float*)(smem + OFF_P);
    float* sB2f = (float*)(smem + OFF_B2);
    int*   sAdj = (int*)(smem + OFF_ADJ);
    float* red  = (float*)(smem + OFF_RED);
    if (tid < H_) sB2f[tid] = b2[tid];

    int cur = 0;
    {
        const char* sh = (const char*)g_Ehi[blockIdx.x];
        for (int i = tid; i < EBYTES/16; i += 256)
            cp16(sb + OFF_E0 + i*16, sh + i*16);
        CP_COMMIT();
    }

    for (int bi = blockIdx.x; bi < NBI; bi += gridDim.x) {
        const int b = bi >> 8;
        const int nbi = bi + gridDim.x;
        float pv = (tid < H_) ? Pg[(size_t)bi*H_ + tid] : 0.f;
        int   av = adj[(size_t)bi*V_ + tid];
        if (nbi < NBI) {
            const int nb = 1 - cur;
            const char* sh = (const char*)g_Ehi[nbi];
            for (int i = tid; i < EBYTES/16; i += 256)
                cp16(sb + OFF_E0 + nb*EBYTES + i*16, sh + i*16);
            CP_COMMIT();
            CP_WAIT1();
        } else {
            CP_WAIT0();
        }
        if (tid < H_) sPf[tid] = pv;
        sAdj[tid] = av;
        __syncthreads();

        const uint32_t eH = sb + OFF_E0 + cur*EBYTES;

        // ---- phase 1 + epilogue 1 per chunk -> aH2[2][8][4] (R12) ----
        uint32_t aH2[2][8][4];
        #pragma unroll
        for (int chunk = 0; chunk < 2; ++chunk) {
            const int jbase = chunk * 128;
            float acc[16][4];
            #pragma unroll
            for (int n = 0; n < 16; ++n)
                #pragma unroll
                for (int p = 0; p < 4; ++p) acc[n][p] = 0.f;

            #pragma unroll
            for (int ks = 0; ks < 2; ++ks) {
                const int k0 = ks * 16;
                uint32_t aH[4];
                uint32_t ao = (uint32_t)((jbase + j0 + rowsel)*ST_E2 + k0 + colsel) * 2u;
                ldsm4(aH, eH + ao);
                const uint32_t brow = (uint32_t)((k0 + rowsel)*ST_W + colsel) * 2u;
                #pragma unroll
                for (int ntp = 0; ntp < 8; ++ntp) {
                    uint32_t bH[4];
                    ldsm4t(bH, sb + OFF_W1HI + brow + (uint32_t)(ntp*16*2));
                    mma_f16(acc[2*ntp],   aH, &bH[0]);
                    mma_f16(acc[2*ntp+1], aH, &bH[2]);
                }
            }

            const float* qA = Qg + ((size_t)(b*V_ + jbase + j0 + g))*H_;
            const float* qB = qA + 8*H_;
            #pragma unroll
            for (int ks = 0; ks < 8; ++ks) {
                #pragma unroll
                for (int h = 0; h < 2; ++h) {
                    const int nt = 2*ks + h;
                    const int c = nt*8 + tg*2;
                    float2 q0 = *(const float2*)(qA + c);
                    float2 q1 = *(const float2*)(qB + c);
                    float pc0 = sPf[c], pc1 = sPf[c+1];
                    float t0 = fmaxf(acc[nt][0] + pc0 + q0.x, 0.f);
                    float t1 = fmaxf(acc[nt][1] + pc1 + q0.y, 0.f);
                    float t2 = fmaxf(acc[nt][2] + pc0 + q1.x, 0.f);
                    float t3 = fmaxf(acc[nt][3] + pc1 + q1.y, 0.f);
                    aH2[chunk][ks][0 + 2*h] = (uint32_t)f16b(t0) | ((uint32_t)f16b(t1) << 16);
                    aH2[chunk][ks][1 + 2*h] = (uint32_t)f16b(t2) | ((uint32_t)f16b(t3) << 16);
                }
            }
        }

        float rmax[32];
        #pragma unroll
        for (int i = 0; i < 32; ++i) rmax[i] = -1e9f;

        const bool actA0 = sAdj[j0 + g] > 0,        actB0 = sAdj[j0 + 8 + g] > 0;
        const bool actA1 = sAdj[128 + j0 + g] > 0,  actB1 = sAdj[128 + j0 + 8 + g] > 0;

        // ---- phase 2 combined (R12): each W2 fragment loaded once ----
        #pragma unroll
        for (int half = 0; half < 2; ++half) {
            float a0[8][4], a1[8][4];
            #pragma unroll
            for (int n = 0; n < 8; ++n)
                #pragma unroll
                for (int p = 0; p < 4; ++p) { a0[n][p] = 0.f; a1[n][p] = 0.f; }

            #pragma unroll
            for (int ks = 0; ks < 8; ++ks) {
                const uint32_t brow =
                    (uint32_t)((ks*16 + rowsel)*ST_W + half*64 + colsel) * 2u;
                #pragma unroll
                for (int ntp = 0; ntp < 4; ++ntp) {
                    uint32_t bH[4];
                    ldsm4t(bH, sb + OFF_W2HI + brow + (uint32_t)(ntp*16*2));
                    mma_f16(a0[2*ntp],   aH2[0][ks], &bH[0]);
                    mma_f16(a0[2*ntp+1], aH2[0][ks], &bH[2]);
                    mma_f16(a1[2*ntp],   aH2[1][ks], &bH[0]);
                    mma_f16(a1[2*ntp+1], aH2[1][ks], &bH[2]);
                }
            }

            #pragma unroll
            for (int nt = 0; nt < 8; ++nt) {
                const int gnt = half*8 + nt;
                const int c = gnt*8 + tg*2;
                float b0 = sB2f[c], b1 = sB2f[c+1];
                if (actA0) {
                    rmax[2*gnt]   = fmaxf(rmax[2*gnt],   fmaxf(a0[nt][0]+b0, 0.f));
                    rmax[2*gnt+1] = fmaxf(rmax[2*gnt+1], fmaxf(a0[nt][1]+b1, 0.f));
                }
                if (actB0) {
                    rmax[2*gnt]   = fmaxf(rmax[2*gnt],   fmaxf(a0[nt][2]+b0, 0.f));
                    rmax[2*gnt+1] = fmaxf(rmax[2*gnt+1], fmaxf(a0[nt][3]+b1, 0.f));
                }
                if (actA1) {
                    rmax[2*gnt]   = fmaxf(rmax[2*gnt],   fmaxf(a1[nt][0]+b0, 0.f));
                    rmax[2*gnt+1] = fmaxf(rmax[2*gnt+1], fmaxf(a1[nt][1]+b1, 0.f));
                }
                if (actB1) {
                    rmax[2*gnt]   = fmaxf(rmax[2*gnt],   fmaxf(a1[nt][2]+b0, 0.f));
                    rmax[2*gnt+1] = fmaxf(rmax[2*gnt+1], fmaxf(a1[nt][3]+b1, 0.f));
                }
            }
        }

        // reduce over g, then over warps via smem
        #pragma unroll
        for (int off = 4; off <= 16; off <<= 1)
            #pragma unroll
            for (int i = 0; i < 32; ++i)
                rmax[i] = fmaxf(rmax[i], __shfl_xor_sync(0xffffffffu, rmax[i], off));

        if (lane < 4) {
            #pragma unroll
            for (int nt = 0; nt < 16; ++nt) {
                red[w*H_ + nt*8 + lane*2]     = rmax[2*nt];
                red[w*H_ + nt*8 + lane*2 + 1] = rmax[2*nt+1];
            }
        }
        __syncthreads();
        if (tid < H_) {
            float v = red[tid];
            #pragma unroll
            for (int ww = 1; ww < 8; ++ww) v = fmaxf(v, red[ww*H_ + tid]);
            v = (v < -1e8f) ? 0.f : v;
            red[tid] = v;   // thread t is the only reader of column t above
        }
        __syncthreads();

        // ---- fused tail: pq (layer 0) or rs (layer 1) from red[0..127] ----
        if (layer == 0) {
            const __half* sWd = (const __half*)(smem + OFF_TW);
            const __half* sWb = (const __half*)(smem + OFF_TW + 32768);
            if (tid < 128) {
                const int h = tid;
                float p0 = 0.f, p1 = 0.f;
                #pragma unroll 4
                for (int c = 0; c < 128; c += 2) {
                    p0 += red[c]   * __half2float(sWd[c*128 + h]);
                    p1 += red[c+1] * __half2float(sWd[(c+1)*128 + h]);
                }
                O1[(size_t)bi*H_ + h] = p0 + p1 + bn[h];
            } else {
                const int h = tid - 128;
                float q0 = 0.f, q1 = 0.f;
                #pragma unroll 4
                for (int c = 0; c < 128; c += 2) {
                    q0 += red[c]   * __half2float(sWb[c*128 + h]);
                    q1 += red[c+1] * __half2float(sWb[(c+1)*128 + h]);
                }
                O2[(size_t)bi*H_ + h] = q0 + q1;
            }
        } else {
            const __half* sWa  = (const __half*)(smem + OFF_TW);
            const __half* sWb2 = (const __half*)(smem + OFF_TW + 65536);
            const int m = tid;
            float r0 = 0.f, r1 = 0.f, s0 = 0.f, s1 = 0.f;
            #pragma unroll 4
            for (int c = 0; c < 128; c += 2) {
                float x0 = red[c], x1 = red[c+1];
                r0 += x0 * __half2float(sWa[c*256 + m]);
                r1 += x1 * __half2float(sWa[(c+1)*256 + m]);
                s0 += x0 * __half2float(sWb2[c*256 + m]);
                s1 += x1 * __half2float(sWb2[(c+1)*256 + m]);
            }
            O1[(size_t)bi*H2_ + m] = r0 + r1;
            O2[(size_t)bi*H2_ + m] = s0 + s1 + bn[m];
        }
        __syncthreads();
        cur ^= 1;
    }
}

// ---------------------------------------------------------------------------
#define IL_ 8
#define MC_ 32
__global__ void __launch_bounds__(256)
pair_kernel(const float* __restrict__ R, const float* __restrict__ S,
            const float* __restrict__ outW, const float* __restrict__ outB,
            float* __restrict__ out)
{
    __shared__ float sR[V_][MC_+1];
    __shared__ float sS[IL_][MC_+1];
    __shared__ float sw[MC_];
    const int tid = threadIdx.x;
    const int b = blockIdx.y, i0 = blockIdx.x * IL_;
    float acc[IL_];
    #pragma unroll
    for (int il = 0; il < IL_; ++il) acc[il] = 0.f;

    for (int mc = 0; mc < H2_; mc += MC_) {
        __syncthreads();
        #pragma unroll 4
        for (int idx = tid; idx < V_*MC_; idx += 256) {
            int j = idx >> 5, mm = idx & (MC_-1);
            sR[j][mm] = R[((size_t)b*V_ + j)*H2_ + mc + mm];
        }
        if (tid < IL_*MC_) {
            int il = tid >> 5, mm = tid & (MC_-1);
            sS[il][mm] = S[((size_t)b*V_ + i0 + il)*H2_ + mc + mm];
        }
        if (tid < MC_) sw[tid] = outW[mc + tid];
        __syncthreads();
        #pragma unroll
        for (int il = 0; il < IL_; ++il) {
            float a = 0.f;
            #pragma unroll
            for (int mm = 0; mm < MC_; ++mm)
                a += fmaxf(sR[tid][mm] + sS[il][mm], 0.f) * sw[mm];
            acc[il] += a;
        }
    }
    const float ob = outB[0];
    #pragma unroll
    for (int il = 0; il < IL_; ++il) {
        float z = acc[il] + ob;
        out[((size_t)b*V_ + i0 + il)*V_ + tid] = 1.f / (1.f + expf(-z));
    }
}

// ---------------------------------------------------------------------------
extern "C" void kernel_launch(void* const* d_in, const int* in_sizes, int n_in,
                              void* d_out, int out_size)
{
    const int*   adj   = (const int*)  d_in[0];
    const float* x0    = (const float*)d_in[1];
    const float* e     = (const float*)d_in[2];
    const float* ec1W1 = (const float*)d_in[3];
    const float* ec1b1 = (const float*)d_in[4];
    const float* ec1W2 = (const float*)d_in[5];
    const float* ec1b2 = (const float*)d_in[6];
    const float* ec2W1 = (const float*)d_in[7];
    const float* ec2b1 = (const float*)d_in[8];
    const float* ec2W2 = (const float*)d_in[9];
    const float* ec2b2 = (const float*)d_in[10];
    const float* h3W   = (const float*)d_in[11];
    const float* h3b   = (const float*)d_in[12];
    const float* outW  = (const float*)d_in[13];
    const float* outB  = (const float*)d_in[14];
    float* out = (float*)d_out;

    float *P, *Q, *P2, *Q2, *R, *S;
    cudaGetSymbolAddress((void**)&P,  g_P);
    cudaGetSymbolAddress((void**)&Q,  g_Q);
    cudaGetSymbolAddress((void**)&P2, g_P2);
    cudaGetSymbolAddress((void**)&Q2, g_Q2);
    cudaGetSymbolAddress((void**)&R,  g_R);
    cudaGetSymbolAddress((void**)&S,  g_S);

    cudaFuncSetAttribute(ec_hmma, cudaFuncAttributeMaxDynamicSharedMemorySize, SMEM_EC1);

    int sms = 148;
    cudaDeviceGetAttribute(&sms, cudaDevAttrMultiProcessorCount, 0);
    int grid = sms < NBI ? sms : NBI;

    // prep: E convert + mainloop weights + tail weights + pq layer 1
    prep_all<<<NBI + 352 + 256, 256>>>(e, ec1W1, ec1W2, ec2W1, ec2W2, h3W,
                                       x0, ec1b1, P, Q);

    // ec layer 0: consumes (P,Q); fused tail writes (P2,Q2) for layer 2
    ec_hmma<<<grid, 256, SMEM_EC0>>>(P, Q, ec1b2, adj, ec2b1, P2, Q2, 0);

    // ec layer 1: consumes (P2,Q2); fused tail writes (R,S) for pair MLP
    ec_hmma<<<grid, 256, SMEM_EC1>>>(P2, Q2, ec2b2, adj, h3b, R, S, 1);

    dim3 pg(V_/IL_, B_);
    pair_kernel<<<pg, 256>>>(R, S, outW, outB, out);
}

// round 16
// speedup vs baseline: 1.1598x; 1.0811x over previous
#include <cuda_runtime.h>
#include <cuda_fp16.h>
#include <cstdint>

#define B_   4
#define V_   256
#define H_   128
#define KE_  32
#define H2_  256
#define ST_W 136
#define ST_E2 40
#define NBI  (B_*V_)
#define ETILE 10240
#define EBYTES 20480

__device__ float g_P [NBI*H_];
__device__ float g_Q [NBI*H_];
__device__ float g_P2[NBI*H_];
__device__ float g_Q2[NBI*H_];
__device__ float g_R [NBI*H2_];
__device__ float g_S [NBI*H2_];
__device__ __align__(16) unsigned short g_w1hi[2][KE_*ST_W];
__device__ __align__(16) unsigned short g_w2hi[2][H_*ST_W];
__device__ __align__(16) unsigned short g_Ehi[NBI][ETILE];
__device__ __align__(16) unsigned short g_tw0d[128*128];
__device__ __align__(16) unsigned short g_tw0b[128*128];
__device__ __align__(16) unsigned short g_tw1a[128*256];
__device__ __align__(16) unsigned short g_tw1b[128*256];

__device__ __forceinline__ unsigned short f16b(float f) {
    __half h = __float2half_rn(f);
    return *(unsigned short*)&h;
}
__device__ __forceinline__ uint32_t smem_to_u32(const void* p) {
    uint32_t a;
    asm("{ .reg .u64 t; cvta.to.shared.u64 t, %1; cvt.u32.u64 %0, t; }" : "=r"(a) : "l"(p));
    return a;
}
__device__ __forceinline__ void ldsm4(uint32_t* r, uint32_t a) {
    asm volatile("ldmatrix.sync.aligned.m8n8.x4.shared.b16 {%0,%1,%2,%3}, [%4];"
        : "=r"(r[0]), "=r"(r[1]), "=r"(r[2]), "=r"(r[3]) : "r"(a));
}
__device__ __forceinline__ void ldsm4t(uint32_t* r, uint32_t a) {
    asm volatile("ldmatrix.sync.aligned.m8n8.x4.trans.shared.b16 {%0,%1,%2,%3}, [%4];"
        : "=r"(r[0]), "=r"(r[1]), "=r"(r[2]), "=r"(r[3]) : "r"(a));
}
__device__ __forceinline__ void mma_f16(float* c, const uint32_t* a, const uint32_t* b) {
    asm volatile("mma.sync.aligned.m16n8k16.row.col.f32.f16.f16.f32 "
        "{%0,%1,%2,%3}, {%4,%5,%6,%7}, {%8,%9}, {%0,%1,%2,%3};"
        : "+f"(c[0]), "+f"(c[1]), "+f"(c[2]), "+f"(c[3])
        : "r"(a[0]), "r"(a[1]), "r"(a[2]), "r"(a[3]), "r"(b[0]), "r"(b[1]));
}
__device__ __forceinline__ void cp16(uint32_t dst, const void* src) {
    asm volatile("cp.async.cg.shared.global [%0], [%1], 16;" :: "r"(dst), "l"(src));
}
#define CP_COMMIT() asm volatile("cp.async.commit_group;" ::: "memory")
#define CP_WAIT1()  asm volatile("cp.async.wait_group 1;" ::: "memory")
#define CP_WAIT0()  asm volatile("cp.async.wait_group 0;" ::: "memory")

// SMEM byte offsets (ec kernel)
#define OFF_B2    0
#define OFF_P     512
#define OFF_ADJ   1024
#define OFF_RED   2048
#define OFF_W1HI  6144
#define OFF_W2HI  14848
#define OFF_E0    49664
#define OFF_TW    (OFF_E0 + 2*EBYTES)          // 90624
#define SMEM_EC0  (OFF_TW + 2*32768)           // 156160
#define SMEM_EC1  (OFF_TW + 2*65536)           // 221696

// ---------------------------------------------------------------------------
__device__ __forceinline__ void pq_impl(int group, const float* __restrict__ x,
                                        const float* __restrict__ W1,
                                        const float* __restrict__ b1, int C_in,
                                        float* __restrict__ P, float* __restrict__ Q)
{
    __shared__ float sx[4][128];
    __shared__ float sp[2][4][128], sq[2][4][128];
    const int tid = threadIdx.x;
    const int cs = tid >> 7, h = tid & 127;
    const int base = group * 4;
    const int lg = (C_in == 64) ? 6 : 7;
    for (int i = tid; i < 4*C_in; i += 256)
        sx[i >> lg][i & (C_in-1)] = x[(size_t)(base + (i >> lg))*C_in + (i & (C_in-1))];
    __syncthreads();

    const int c0 = cs * (C_in >> 1), c1 = c0 + (C_in >> 1);
    float p[4] = {0.f,0.f,0.f,0.f}, q[4] = {0.f,0.f,0.f,0.f};
    for (int c = c0; c < c1; ++c) {
        float wa = W1[c*H_ + h], wb = W1[(C_in+c)*H_ + h], wd = wa - wb;
        #pragma unroll
        for (int r = 0; r < 4; ++r) { p[r] += sx[r][c]*wd; q[r] += sx[r][c]*wb; }
    }
    #pragma unroll
    for (int r = 0; r < 4; ++r) { sp[cs][r][h] = p[r]; sq[cs][r][h] = q[r]; }
    __syncthreads();
    if (cs == 0) {
        float bb = b1[h];
        #pragma unroll
        for (int r = 0; r < 4; ++r) {
            P[(size_t)(base+r)*H_ + h] = sp[0][r][h] + sp[1][r][h] + bb;
            Q[(size_t)(base+r)*H_ + h] = sq[0][r][h] + sq[1][r][h];
        }
    }
}

__global__ void prep_all(const float* __restrict__ E,
                         const float* __restrict__ W1a, const float* __restrict__ W2a,
                         const float* __restrict__ W1b, const float* __restrict__ W2b,
                         const float* __restrict__ h3W,
                         const float* __restrict__ x0,  const float* __restrict__ b1a,
                         float* __restrict__ P, float* __restrict__ Q)
{
    const int blk = blockIdx.x, tid = threadIdx.x;
    if (blk < NBI) {
        unsigned short* eh = g_Ehi[blk];
        for (int idx = tid; idx < 2048; idx += 256) {
            int j = idx >> 3, kq = idx & 7;
            float4 e4 = *(const float4*)(E + ((size_t)blk*V_ + j)*KE_ + kq*4);
            uint2 hp;
            hp.x = (uint32_t)f16b(e4.x) | ((uint32_t)f16b(e4.y) << 16);
            hp.y = (uint32_t)f16b(e4.z) | ((uint32_t)f16b(e4.w) << 16);
            *(uint2*)(eh + j*ST_E2 + kq*4) = hp;
        }
    } else if (blk < NBI + 160) {
        int idx = (blk - NBI) * 256 + tid;
        if (idx < 40960) {
            int layer = idx / 20480;
            int t = idx - layer * 20480;
            const float* W1 = layer ? W1b : W1a;
            const float* W2 = layer ? W2b : W2a;
            const int C = layer ? 128 : 64;
            if (t < KE_*H_) {
                int k = t >> 7, c = t & 127;
                g_w1hi[layer][k*ST_W + c] = f16b(W1[(size_t)(2*C + k)*H_ + c]);
            } else {
                int t2 = t - KE_*H_;
                int k = t2 >> 7, c = t2 & 127;
                g_w2hi[layer][k*ST_W + c] = f16b(W2[(size_t)k*H_ + c]);
            }
        }
    } else if (blk < NBI + 160 + 64) {
        int idx = (blk - (NBI + 160)) * 256 + tid;
        int c = idx >> 7, h = idx & 127;
        float wa = W1b[(size_t)c*H_ + h];
        float wb = W1b[(size_t)(128 + c)*H_ + h];
        g_tw0d[idx] = f16b(wa - wb);
        g_tw0b[idx] = f16b(wb);
    } else if (blk < NBI + 160 + 64 + 128) {
        int idx = (blk - (NBI + 160 + 64)) * 256 + tid;
        int c = idx >> 8, m = idx & 255;
        g_tw1a[idx] = f16b(h3W[(size_t)c*H2_ + m]);
        g_tw1b[idx] = f16b(h3W[(size_t)(128 + c)*H2_ + m]);
    } else {
        pq_impl(blk - (NBI + 352), x0, W1a, b1a, 64, P, Q);
    }
}

// ---------------------------------------------------------------------------
// Persistent-CTA fused EdgeConv (R12 mainloop) + fused pq/rs tail (R15).
// ---------------------------------------------------------------------------
__global__ void __launch_bounds__(256, 1)
ec_hmma(const float* __restrict__ Pg, const float* __restrict__ Qg,
        const float* __restrict__ b2, const int* __restrict__ adj,
        const float* __restrict__ bn,
        float* __restrict__ O1, float* __restrict__ O2, int layer)
{
    extern __shared__ char smem[];
    const uint32_t sb = smem_to_u32(smem);
    const int tid = threadIdx.x, w = tid >> 5, lane = tid & 31;
    const int g = lane >> 2, tg = lane & 3;
    const int j0 = w * 16;
    const int rowsel = lane & 15, colsel = (lane >> 4) * 8;

    {
        const uint4* s; uint4* d;
        s = (const uint4*)g_w1hi[layer]; d = (uint4*)(smem + OFF_W1HI);
        for (int i = tid; i < 544;  i += 256) d[i] = s[i];
        s = (const uint4*)g_w2hi[layer]; d = (uint4*)(smem + OFF_W2HI);
        for (int i = tid; i < 2176; i += 256) d[i] = s[i];
        const int twb = (layer == 0) ? 32768 : 65536;
        const uint4* sa = (layer == 0) ? (const uint4*)g_tw0d : (const uint4*)g_tw1a;
        const uint4* sbp = (layer == 0) ? (const uint4*)g_tw0b : (const uint4*)g_tw1b;
        uint4* da = (uint4*)(smem + OFF_TW);
        uint4* db = (uint4*)(smem + OFF_TW + twb);
        for (int i = tid; i < twb/16; i += 256) { da[i] = sa[i]; db[i] = sbp[i]; }
    }
    float* sPf  = (float*)(smem + OFF_P);
    float* sB2f = (float*)(smem + OFF_B2);
    int*   sAdj = (int*)(smem + OFF_ADJ);
    float* red  = (float*)(smem + OFF_RED);
    if (tid < H_) sB2f[tid] = b2[tid];

    int cur = 0;
    {
        const char* sh = (const char*)g_Ehi[blockIdx.x];
        for (int i = tid; i < EBYTES/16; i += 256)
            cp16(sb + OFF_E0 + i*16, sh + i*16);
        CP_COMMIT();
    }

    for (int bi = blockIdx.x; bi < NBI; bi += gridDim.x) {
        const int b = bi >> 8;
        const int nbi = bi + gridDim.x;
        float pv = (tid < H_) ? Pg[(size_t)bi*H_ + tid] : 0.f;
        int   av = adj[(size_t)bi*V_ + tid];
        if (nbi < NBI) {
            const int nb = 1 - cur;
            const char* sh = (const char*)g_Ehi[nbi];
            for (int i = tid; i < EBYTES/16; i += 256)
                cp16(sb + OFF_E0 + nb*EBYTES + i*16, sh + i*16);
            CP_COMMIT();
            CP_WAIT1();
        } else {
            CP_WAIT0();
        }
        if (tid < H_) sPf[tid] = pv;
        sAdj[tid] = av;
        __syncthreads();

        const uint32_t eH = sb + OFF_E0 + cur*EBYTES;

        uint32_t aH2[2][8][4];
        #pragma unroll
        for (int chunk = 0; chunk < 2; ++chunk) {
            const int jbase = chunk * 128;
            float acc[16][4];
            #pragma unroll
            for (int n = 0; n < 16; ++n)
                #pragma unroll
                for (int p = 0; p < 4; ++p) acc[n][p] = 0.f;

            #pragma unroll
            for (int ks = 0; ks < 2; ++ks) {
                const int k0 = ks * 16;
                uint32_t aH[4];
                uint32_t ao = (uint32_t)((jbase + j0 + rowsel)*ST_E2 + k0 + colsel) * 2u;
                ldsm4(aH, eH + ao);
                const uint32_t brow = (uint32_t)((k0 + rowsel)*ST_W + colsel) * 2u;
                #pragma unroll
                for (int ntp = 0; ntp < 8; ++ntp) {
                    uint32_t bH[4];
                    ldsm4t(bH, sb + OFF_W1HI + brow + (uint32_t)(ntp*16*2));
                    mma_f16(acc[2*ntp],   aH, &bH[0]);
                    mma_f16(acc[2*ntp+1], aH, &bH[2]);
                }
            }

            const float* qA = Qg + ((size_t)(b*V_ + jbase + j0 + g))*H_;
            const float* qB = qA + 8*H_;
            #pragma unroll
            for (int ks = 0; ks < 8; ++ks) {
                #pragma unroll
                for (int h = 0; h < 2; ++h) {
                    const int nt = 2*ks + h;
                    const int c = nt*8 + tg*2;
                    float2 q0 = *(const float2*)(qA + c);
                    float2 q1 = *(const float2*)(qB + c);
                    float pc0 = sPf[c], pc1 = sPf[c+1];
                    float t0 = fmaxf(acc[nt][0] + pc0 + q0.x, 0.f);
                    float t1 = fmaxf(acc[nt][1] + pc1 + q0.y, 0.f);
                    float t2 = fmaxf(acc[nt][2] + pc0 + q1.x, 0.f);
                    float t3 = fmaxf(acc[nt][3] + pc1 + q1.y, 0.f);
                    aH2[chunk][ks][0 + 2*h] = (uint32_t)f16b(t0) | ((uint32_t)f16b(t1) << 16);
                    aH2[chunk][ks][1 + 2*h] = (uint32_t)f16b(t2) | ((uint32_t)f16b(t3) << 16);
                }
            }
        }

        float rmax[32];
        #pragma unroll
        for (int i = 0; i < 32; ++i) rmax[i] = -1e9f;

        const bool actA0 = sAdj[j0 + g] > 0,        actB0 = sAdj[j0 + 8 + g] > 0;
        const bool actA1 = sAdj[128 + j0 + g] > 0,  actB1 = sAdj[128 + j0 + 8 + g] > 0;

        #pragma unroll
        for (int half = 0; half < 2; ++half) {
            float a0[8][4], a1[8][4];
            #pragma unroll
            for (int n = 0; n < 8; ++n)
                #pragma unroll
                for (int p = 0; p < 4; ++p) { a0[n][p] = 0.f; a1[n][p] = 0.f; }

            #pragma unroll
            for (int ks = 0; ks < 8; ++ks) {
                const uint32_t brow =
                    (uint32_t)((ks*16 + rowsel)*ST_W + half*64 + colsel) * 2u;
                #pragma unroll
                for (int ntp = 0; ntp < 4; ++ntp) {
                    uint32_t bH[4];
                    ldsm4t(bH, sb + OFF_W2HI + brow + (uint32_t)(ntp*16*2));
                    mma_f16(a0[2*ntp],   aH2[0][ks], &bH[0]);
                    mma_f16(a0[2*ntp+1], aH2[0][ks], &bH[2]);
                    mma_f16(a1[2*ntp],   aH2[1][ks], &bH[0]);
                    mma_f16(a1[2*ntp+1], aH2[1][ks], &bH[2]);
                }
            }

            #pragma unroll
            for (int nt = 0; nt < 8; ++nt) {
                const int gnt = half*8 + nt;
                const int c = gnt*8 + tg*2;
                float b0 = sB2f[c], b1 = sB2f[c+1];
                if (actA0) {
                    rmax[2*gnt]   = fmaxf(rmax[2*gnt],   fmaxf(a0[nt][0]+b0, 0.f));
                    rmax[2*gnt+1] = fmaxf(rmax[2*gnt+1], fmaxf(a0[nt][1]+b1, 0.f));
                }
                if (actB0) {
                    rmax[2*gnt]   = fmaxf(rmax[2*gnt],   fmaxf(a0[nt][2]+b0, 0.f));
                    rmax[2*gnt+1] = fmaxf(rmax[2*gnt+1], fmaxf(a0[nt][3]+b1, 0.f));
                }
                if (actA1) {
                    rmax[2*gnt]   = fmaxf(rmax[2*gnt],   fmaxf(a1[nt][0]+b0, 0.f));
                    rmax[2*gnt+1] = fmaxf(rmax[2*gnt+1], fmaxf(a1[nt][1]+b1, 0.f));
                }
                if (actB1) {
                    rmax[2*gnt]   = fmaxf(rmax[2*gnt],   fmaxf(a1[nt][2]+b0, 0.f));
                    rmax[2*gnt+1] = fmaxf(rmax[2*gnt+1], fmaxf(a1[nt][3]+b1, 0.f));
                }
            }
        }

        #pragma unroll
        for (int off = 4; off <= 16; off <<= 1)
            #pragma unroll
            for (int i = 0; i < 32; ++i)
                rmax[i] = fmaxf(rmax[i], __shfl_xor_sync(0xffffffffu, rmax[i], off));

        if (lane < 4) {
            #pragma unroll
            for (int nt = 0; nt < 16; ++nt) {
                red[w*H_ + nt*8 + lane*2]     = rmax[2*nt];
                red[w*H_ + nt*8 + lane*2 + 1] = rmax[2*nt+1];
            }
        }
        __syncthreads();
        if (tid < H_) {
            float v = red[tid];
            #pragma unroll
            for (int ww = 1; ww < 8; ++ww) v = fmaxf(v, red[ww*H_ + tid]);
            v = (v < -1e8f) ? 0.f : v;
            red[tid] = v;
        }
        __syncthreads();

        if (layer == 0) {
            const __half* sWd = (const __half*)(smem + OFF_TW);
            const __half* sWb = (const __half*)(smem + OFF_TW + 32768);
            if (tid < 128) {
                const int h = tid;
                float p0 = 0.f, p1 = 0.f;
                #pragma unroll 4
                for (int c = 0; c < 128; c += 2) {
                    p0 += red[c]   * __half2float(sWd[c*128 + h]);
                    p1 += red[c+1] * __half2float(sWd[(c+1)*128 + h]);
                }
                O1[(size_t)bi*H_ + h] = p0 + p1 + bn[h];
            } else {
                const int h = tid - 128;
                float q0 = 0.f, q1 = 0.f;
                #pragma unroll 4
                for (int c = 0; c < 128; c += 2) {
                    q0 += red[c]   * __half2float(sWb[c*128 + h]);
                    q1 += red[c+1] * __half2float(sWb[(c+1)*128 + h]);
                }
                O2[(size_t)bi*H_ + h] = q0 + q1;
            }
        } else {
            const __half* sWa  = (const __half*)(smem + OFF_TW);
            const __half* sWb2 = (const __half*)(smem + OFF_TW + 65536);
            const int m = tid;
            float r0 = 0.f, r1 = 0.f, s0 = 0.f, s1 = 0.f;
            #pragma unroll 4
            for (int c = 0; c < 128; c += 2) {
                float x0 = red[c], x1 = red[c+1];
                r0 += x0 * __half2float(sWa[c*256 + m]);
                r1 += x1 * __half2float(sWa[(c+1)*256 + m]);
                s0 += x0 * __half2float(sWb2[c*256 + m]);
                s1 += x1 * __half2float(sWb2[(c+1)*256 + m]);
            }
            O1[(size_t)bi*H2_ + m] = r0 + r1;
            O2[(size_t)bi*H2_ + m] = s0 + s1 + bn[m];
        }
        __syncthreads();
        cur ^= 1;
    }
}

// ---------------------------------------------------------------------------
// pair: LDS-issue-optimized. 512 threads = 2 il-groups x 256 j.
// R rows / S rows / w chunk register-cached via LDS.128 (stride-36 pad).
// ---------------------------------------------------------------------------
#define PIL 8
#define PST 36
__global__ void __launch_bounds__(512)
pair_kernel(const float* __restrict__ R, const float* __restrict__ S,
            const float* __restrict__ outW, const float* __restrict__ outB,
            float* __restrict__ out)
{
    __shared__ float sR[V_*PST];
    __shared__ float sS[PIL*PST];
    __shared__ float sw[32];
    const int tid = threadIdx.x;
    const int j = tid & 255;
    const int ig = tid >> 8;            // il group: 0 -> il 0..3, 1 -> il 4..7
    const int b = blockIdx.y, i0 = blockIdx.x * PIL;

    float acc[4] = {0.f, 0.f, 0.f, 0.f};

    for (int mc = 0; mc < H2_; mc += 32) {
        __syncthreads();
        // stage R chunk: 256 rows x 32 floats (2048 float4)
        for (int idx = tid; idx < 2048; idx += 512) {
            int row = idx >> 3, c4 = idx & 7;
            float4 v = *(const float4*)(R + ((size_t)(b*V_ + row))*H2_ + mc + c4*4);
            *(float4*)&sR[row*PST + c4*4] = v;
        }
        if (tid < PIL*8) {
            int row = tid >> 3, c4 = tid & 7;
            float4 v = *(const float4*)(S + ((size_t)(b*V_ + i0 + row))*H2_ + mc + c4*4);
            *(float4*)&sS[row*PST + c4*4] = v;
        }
        if (tid < 32) sw[tid] = outW[mc + tid];
        __syncthreads();

        float rr[32], wv[32];
        #pragma unroll
        for (int k = 0; k < 8; ++k) {
            *(float4*)&rr[k*4] = *(const float4*)&sR[j*PST + k*4];
            *(float4*)&wv[k*4] = *(const float4*)&sw[k*4];
        }
        #pragma unroll
        for (int il = 0; il < 4; ++il) {
            float ss[32];
            #pragma unroll
            for (int k = 0; k < 8; ++k)
                *(float4*)&ss[k*4] = *(const float4*)&sS[(ig*4 + il)*PST + k*4];
            float a = 0.f;
            #pragma unroll
            for (int mm = 0; mm < 32; ++mm)
                a += fmaxf(rr[mm] + ss[mm], 0.f) * wv[mm];
            acc[il] += a;
        }
    }
    const float ob = outB[0];
    #pragma unroll
    for (int il = 0; il < 4; ++il) {
        float z = acc[il] + ob;
        out[((size_t)(b*V_ + i0 + ig*4 + il))*V_ + j] = 1.f / (1.f + expf(-z));
    }
}

// ---------------------------------------------------------------------------
extern "C" void kernel_launch(void* const* d_in, const int* in_sizes, int n_in,
                              void* d_out, int out_size)
{
    const int*   adj   = (const int*)  d_in[0];
    const float* x0    = (const float*)d_in[1];
    const float* e     = (const float*)d_in[2];
    const float* ec1W1 = (const float*)d_in[3];
    const float* ec1b1 = (const float*)d_in[4];
    const float* ec1W2 = (const float*)d_in[5];
    const float* ec1b2 = (const float*)d_in[6];
    const float* ec2W1 = (const float*)d_in[7];
    const float* ec2b1 = (const float*)d_in[8];
    const float* ec2W2 = (const float*)d_in[9];
    const float* ec2b2 = (const float*)d_in[10];
    const float* h3W   = (const float*)d_in[11];
    const float* h3b   = (const float*)d_in[12];
    const float* outW  = (const float*)d_in[13];
    const float* outB  = (const float*)d_in[14];
    float* out = (float*)d_out;

    float *P, *Q, *P2, *Q2, *R, *S;
    cudaGetSymbolAddress((void**)&P,  g_P);
    cudaGetSymbolAddress((void**)&Q,  g_Q);
    cudaGetSymbolAddress((void**)&P2, g_P2);
    cudaGetSymbolAddress((void**)&Q2, g_Q2);
    cudaGetSymbolAddress((void**)&R,  g_R);
    cudaGetSymbolAddress((void**)&S,  g_S);

    cudaFuncSetAttribute(ec_hmma, cudaFuncAttributeMaxDynamicSharedMemorySize, SMEM_EC1);

    int sms = 148;
    cudaDeviceGetAttribute(&sms, cudaDevAttrMultiProcessorCount, 0);
    int grid = sms < NBI ? sms : NBI;

    prep_all<<<NBI + 352 + 256, 256>>>(e, ec1W1, ec1W2, ec2W1, ec2W2, h3W,
                                       x0, ec1b1, P, Q);

    ec_hmma<<<grid, 256, SMEM_EC0>>>(P, Q, ec1b2, adj, ec2b1, P2, Q2, 0);
    ec_hmma<<<grid, 256, SMEM_EC1>>>(P2, Q2, ec2b2, adj, h3b, R, S, 1);

    dim3 pg(V_/PIL, B_);
    pair_kernel<<<pg, 512>>>(R, S, outW, outB, out);
}

// round 17
// speedup vs baseline: 1.1617x; 1.0016x over previous
#include <cuda_runtime.h>
#include <cuda_fp16.h>
#include <cstdint>

#define B_   4
#define V_   256
#define H_   128
#define KE_  32
#define H2_  256
#define ST_W 136
#define ST_E2 40
#define NBI  (B_*V_)
#define ETILE 10240
#define EBYTES 20480

__device__ float g_P [NBI*H_];
__device__ float g_Q [NBI*H_];
__device__ float g_P2[NBI*H_];
__device__ float g_Q2[NBI*H_];
__device__ float g_R [NBI*H2_];
__device__ float g_S [NBI*H2_];
__device__ __align__(16) unsigned short g_w1hi[2][KE_*ST_W];
__device__ __align__(16) unsigned short g_w2hi[2][H_*ST_W];
__device__ __align__(16) unsigned short g_Ehi[NBI][ETILE];
__device__ __align__(16) unsigned short g_tw0d[128*128];
__device__ __align__(16) unsigned short g_tw0b[128*128];
__device__ __align__(16) unsigned short g_tw1a[128*256];
__device__ __align__(16) unsigned short g_tw1b[128*256];

__device__ __forceinline__ unsigned short f16b(float f) {
    __half h = __float2half_rn(f);
    return *(unsigned short*)&h;
}
__device__ __forceinline__ uint32_t smem_to_u32(const void* p) {
    uint32_t a;
    asm("{ .reg .u64 t; cvta.to.shared.u64 t, %1; cvt.u32.u64 %0, t; }" : "=r"(a) : "l"(p));
    return a;
}
__device__ __forceinline__ void ldsm4(uint32_t* r, uint32_t a) {
    asm volatile("ldmatrix.sync.aligned.m8n8.x4.shared.b16 {%0,%1,%2,%3}, [%4];"
        : "=r"(r[0]), "=r"(r[1]), "=r"(r[2]), "=r"(r[3]) : "r"(a));
}
__device__ __forceinline__ void ldsm4t(uint32_t* r, uint32_t a) {
    asm volatile("ldmatrix.sync.aligned.m8n8.x4.trans.shared.b16 {%0,%1,%2,%3}, [%4];"
        : "=r"(r[0]), "=r"(r[1]), "=r"(r[2]), "=r"(r[3]) : "r"(a));
}
__device__ __forceinline__ void mma_f16(float* c, const uint32_t* a, const uint32_t* b) {
    asm volatile("mma.sync.aligned.m16n8k16.row.col.f32.f16.f16.f32 "
        "{%0,%1,%2,%3}, {%4,%5,%6,%7}, {%8,%9}, {%0,%1,%2,%3};"
        : "+f"(c[0]), "+f"(c[1]), "+f"(c[2]), "+f"(c[3])
        : "r"(a[0]), "r"(a[1]), "r"(a[2]), "r"(a[3]), "r"(b[0]), "r"(b[1]));
}
__device__ __forceinline__ void cp16(uint32_t dst, const void* src) {
    asm volatile("cp.async.cg.shared.global [%0], [%1], 16;" :: "r"(dst), "l"(src));
}
#define CP_COMMIT() asm volatile("cp.async.commit_group;" ::: "memory")
#define CP_WAIT1()  asm volatile("cp.async.wait_group 1;" ::: "memory")
#define CP_WAIT0()  asm volatile("cp.async.wait_group 0;" ::: "memory")

// SMEM byte offsets (ec kernel)
#define OFF_B2    0
#define OFF_P     512
#define OFF_ADJ   1024
#define OFF_RED   2048
#define OFF_W1HI  6144
#define OFF_W2HI  14848
#define OFF_E0    49664
#define OFF_TW    (OFF_E0 + 2*EBYTES)          // 90624
#define SMEM_EC0  (OFF_TW + 2*32768)           // 156160
#define SMEM_EC1  (OFF_TW + 2*65536)           // 221696

// ---------------------------------------------------------------------------
__device__ __forceinline__ void pq_impl(int group, const float* __restrict__ x,
                                        const float* __restrict__ W1,
                                        const float* __restrict__ b1, int C_in,
                                        float* __restrict__ P, float* __restrict__ Q)
{
    __shared__ float sx[4][128];
    __shared__ float sp[2][4][128], sq[2][4][128];
    const int tid = threadIdx.x;
    const int cs = tid >> 7, h = tid & 127;
    const int base = group * 4;
    const int lg = (C_in == 64) ? 6 : 7;
    for (int i = tid; i < 4*C_in; i += 256)
        sx[i >> lg][i & (C_in-1)] = x[(size_t)(base + (i >> lg))*C_in + (i & (C_in-1))];
    __syncthreads();

    const int c0 = cs * (C_in >> 1), c1 = c0 + (C_in >> 1);
    float p[4] = {0.f,0.f,0.f,0.f}, q[4] = {0.f,0.f,0.f,0.f};
    for (int c = c0; c < c1; ++c) {
        float wa = W1[c*H_ + h], wb = W1[(C_in+c)*H_ + h], wd = wa - wb;
        #pragma unroll
        for (int r = 0; r < 4; ++r) { p[r] += sx[r][c]*wd; q[r] += sx[r][c]*wb; }
    }
    #pragma unroll
    for (int r = 0; r < 4; ++r) { sp[cs][r][h] = p[r]; sq[cs][r][h] = q[r]; }
    __syncthreads();
    if (cs == 0) {
        float bb = b1[h];
        #pragma unroll
        for (int r = 0; r < 4; ++r) {
            P[(size_t)(base+r)*H_ + h] = sp[0][r][h] + sp[1][r][h] + bb;
            Q[(size_t)(base+r)*H_ + h] = sq[0][r][h] + sq[1][r][h];
        }
    }
}

__global__ void prep_all(const float* __restrict__ E,
                         const float* __restrict__ W1a, const float* __restrict__ W2a,
                         const float* __restrict__ W1b, const float* __restrict__ W2b,
                         const float* __restrict__ h3W,
                         const float* __restrict__ x0,  const float* __restrict__ b1a,
                         float* __restrict__ P, float* __restrict__ Q)
{
    const int blk = blockIdx.x, tid = threadIdx.x;
    if (blk < NBI) {
        unsigned short* eh = g_Ehi[blk];
        for (int idx = tid; idx < 2048; idx += 256) {
            int j = idx >> 3, kq = idx & 7;
            float4 e4 = *(const float4*)(E + ((size_t)blk*V_ + j)*KE_ + kq*4);
            uint2 hp;
            hp.x = (uint32_t)f16b(e4.x) | ((uint32_t)f16b(e4.y) << 16);
            hp.y = (uint32_t)f16b(e4.z) | ((uint32_t)f16b(e4.w) << 16);
            *(uint2*)(eh + j*ST_E2 + kq*4) = hp;
        }
    } else if (blk < NBI + 160) {
        int idx = (blk - NBI) * 256 + tid;
        if (idx < 40960) {
            int layer = idx / 20480;
            int t = idx - layer * 20480;
            const float* W1 = layer ? W1b : W1a;
            const float* W2 = layer ? W2b : W2a;
            const int C = layer ? 128 : 64;
            if (t < KE_*H_) {
                int k = t >> 7, c = t & 127;
                g_w1hi[layer][k*ST_W + c] = f16b(W1[(size_t)(2*C + k)*H_ + c]);
            } else {
                int t2 = t - KE_*H_;
                int k = t2 >> 7, c = t2 & 127;
                g_w2hi[layer][k*ST_W + c] = f16b(W2[(size_t)k*H_ + c]);
            }
        }
    } else if (blk < NBI + 160 + 64) {
        int idx = (blk - (NBI + 160)) * 256 + tid;
        int c = idx >> 7, h = idx & 127;
        float wa = W1b[(size_t)c*H_ + h];
        float wb = W1b[(size_t)(128 + c)*H_ + h];
        g_tw0d[idx] = f16b(wa - wb);
        g_tw0b[idx] = f16b(wb);
    } else if (blk < NBI + 160 + 64 + 128) {
        int idx = (blk - (NBI + 160 + 64)) * 256 + tid;
        int c = idx >> 8, m = idx & 255;
        g_tw1a[idx] = f16b(h3W[(size_t)c*H2_ + m]);
        g_tw1b[idx] = f16b(h3W[(size_t)(128 + c)*H2_ + m]);
    } else {
        pq_impl(blk - (NBI + 352), x0, W1a, b1a, 64, P, Q);
    }
}

// ---------------------------------------------------------------------------
// Persistent-CTA fused EdgeConv (R12 mainloop) + fused pq/rs tail (R15).
// ---------------------------------------------------------------------------
__global__ void __launch_bounds__(256, 1)
ec_hmma(const float* __restrict__ Pg, const float* __restrict__ Qg,
        const float* __restrict__ b2, const int* __restrict__ adj,
        const float* __restrict__ bn,
        float* __restrict__ O1, float* __restrict__ O2, int layer)
{
    extern __shared__ char smem[];
    const uint32_t sb = smem_to_u32(smem);
    const int tid = threadIdx.x, w = tid >> 5, lane = tid & 31;
    const int g = lane >> 2, tg = lane & 3;
    const int j0 = w * 16;
    const int rowsel = lane & 15, colsel = (lane >> 4) * 8;

    {
        const uint4* s; uint4* d;
        s = (const uint4*)g_w1hi[layer]; d = (uint4*)(smem + OFF_W1HI);
        for (int i = tid; i < 544;  i += 256) d[i] = s[i];
        s = (const uint4*)g_w2hi[layer]; d = (uint4*)(smem + OFF_W2HI);
        for (int i = tid; i < 2176; i += 256) d[i] = s[i];
        const int twb = (layer == 0) ? 32768 : 65536;
        const uint4* sa = (layer == 0) ? (const uint4*)g_tw0d : (const uint4*)g_tw1a;
        const uint4* sbp = (layer == 0) ? (const uint4*)g_tw0b : (const uint4*)g_tw1b;
        uint4* da = (uint4*)(smem + OFF_TW);
        uint4* db = (uint4*)(smem + OFF_TW + twb);
        for (int i = tid; i < twb/16; i += 256) { da[i] = sa[i]; db[i] = sbp[i]; }
    }
    float* sPf  = (float*)(smem + OFF_P);
    float* sB2f = (float*)(smem + OFF_B2);
    int*   sAdj = (int*)(smem + OFF_ADJ);
    float* red  = (float*)(smem + OFF_RED);
    if (tid < H_) sB2f[tid] = b2[tid];

    int cur = 0;
    {
        const char* sh = (const char*)g_Ehi[blockIdx.x];
        for (int i = tid; i < EBYTES/16; i += 256)
            cp16(sb + OFF_E0 + i*16, sh + i*16);
        CP_COMMIT();
    }

    for (int bi = blockIdx.x; bi < NBI; bi += gridDim.x) {
        const int b = bi >> 8;
        const int nbi = bi + gridDim.x;
        float pv = (tid < H_) ? Pg[(size_t)bi*H_ + tid] : 0.f;
        int   av = adj[(size_t)bi*V_ + tid];
        if (nbi < NBI) {
            const int nb = 1 - cur;
            const char* sh = (const char*)g_Ehi[nbi];
            for (int i = tid; i < EBYTES/16; i += 256)
                cp16(sb + OFF_E0 + nb*EBYTES + i*16, sh + i*16);
            CP_COMMIT();
            CP_WAIT1();
        } else {
            CP_WAIT0();
        }
        if (tid < H_) sPf[tid] = pv;
        sAdj[tid] = av;
        __syncthreads();

        const uint32_t eH = sb + OFF_E0 + cur*EBYTES;

        uint32_t aH2[2][8][4];
        #pragma unroll
        for (int chunk = 0; chunk < 2; ++chunk) {
            const int jbase = chunk * 128;
            float acc[16][4];
            #pragma unroll
            for (int n = 0; n < 16; ++n)
                #pragma unroll
                for (int p = 0; p < 4; ++p) acc[n][p] = 0.f;

            #pragma unroll
            for (int ks = 0; ks < 2; ++ks) {
                const int k0 = ks * 16;
                uint32_t aH[4];
                uint32_t ao = (uint32_t)((jbase + j0 + rowsel)*ST_E2 + k0 + colsel) * 2u;
                ldsm4(aH, eH + ao);
                const uint32_t brow = (uint32_t)((k0 + rowsel)*ST_W + colsel) * 2u;
                #pragma unroll
                for (int ntp = 0; ntp < 8; ++ntp) {
                    uint32_t bH[4];
                    ldsm4t(bH, sb + OFF_W1HI + brow + (uint32_t)(ntp*16*2));
                    mma_f16(acc[2*ntp],   aH, &bH[0]);
                    mma_f16(acc[2*ntp+1], aH, &bH[2]);
                }
            }

            const float* qA = Qg + ((size_t)(b*V_ + jbase + j0 + g))*H_;
            const float* qB = qA + 8*H_;
            #pragma unroll
            for (int ks = 0; ks < 8; ++ks) {
                #pragma unroll
                for (int h = 0; h < 2; ++h) {
                    const int nt = 2*ks + h;
                    const int c = nt*8 + tg*2;
                    float2 q0 = *(const float2*)(qA + c);
                    float2 q1 = *(const float2*)(qB + c);
                    float pc0 = sPf[c], pc1 = sPf[c+1];
                    float t0 = fmaxf(acc[nt][0] + pc0 + q0.x, 0.f);
                    float t1 = fmaxf(acc[nt][1] + pc1 + q0.y, 0.f);
                    float t2 = fmaxf(acc[nt][2] + pc0 + q1.x, 0.f);
                    float t3 = fmaxf(acc[nt][3] + pc1 + q1.y, 0.f);
                    aH2[chunk][ks][0 + 2*h] = (uint32_t)f16b(t0) | ((uint32_t)f16b(t1) << 16);
                    aH2[chunk][ks][1 + 2*h] = (uint32_t)f16b(t2) | ((uint32_t)f16b(t3) << 16);
                }
            }
        }

        float rmax[32];
        #pragma unroll
        for (int i = 0; i < 32; ++i) rmax[i] = -1e9f;

        const bool actA0 = sAdj[j0 + g] > 0,        actB0 = sAdj[j0 + 8 + g] > 0;
        const bool actA1 = sAdj[128 + j0 + g] > 0,  actB1 = sAdj[128 + j0 + 8 + g] > 0;

        #pragma unroll
        for (int half = 0; half < 2; ++half) {
            float a0[8][4], a1[8][4];
            #pragma unroll
            for (int n = 0; n < 8; ++n)
                #pragma unroll
                for (int p = 0; p < 4; ++p) { a0[n][p] = 0.f; a1[n][p] = 0.f; }

            #pragma unroll
            for (int ks = 0; ks < 8; ++ks) {
                const uint32_t brow =
                    (uint32_t)((ks*16 + rowsel)*ST_W + half*64 + colsel) * 2u;
                #pragma unroll
                for (int ntp = 0; ntp < 4; ++ntp) {
                    uint32_t bH[4];
                    ldsm4t(bH, sb + OFF_W2HI + brow + (uint32_t)(ntp*16*2));
                    mma_f16(a0[2*ntp],   aH2[0][ks], &bH[0]);
                    mma_f16(a0[2*ntp+1], aH2[0][ks], &bH[2]);
                    mma_f16(a1[2*ntp],   aH2[1][ks], &bH[0]);
                    mma_f16(a1[2*ntp+1], aH2[1][ks], &bH[2]);
                }
            }

            #pragma unroll
            for (int nt = 0; nt < 8; ++nt) {
                const int gnt = half*8 + nt;
                const int c = gnt*8 + tg*2;
                float b0 = sB2f[c], b1 = sB2f[c+1];
                if (actA0) {
                    rmax[2*gnt]   = fmaxf(rmax[2*gnt],   fmaxf(a0[nt][0]+b0, 0.f));
                    rmax[2*gnt+1] = fmaxf(rmax[2*gnt+1], fmaxf(a0[nt][1]+b1, 0.f));
                }
                if (actB0) {
                    rmax[2*gnt]   = fmaxf(rmax[2*gnt],   fmaxf(a0[nt][2]+b0, 0.f));
                    rmax[2*gnt+1] = fmaxf(rmax[2*gnt+1], fmaxf(a0[nt][3]+b1, 0.f));
                }
                if (actA1) {
                    rmax[2*gnt]   = fmaxf(rmax[2*gnt],   fmaxf(a1[nt][0]+b0, 0.f));
                    rmax[2*gnt+1] = fmaxf(rmax[2*gnt+1], fmaxf(a1[nt][1]+b1, 0.f));
                }
                if (actB1) {
                    rmax[2*gnt]   = fmaxf(rmax[2*gnt],   fmaxf(a1[nt][2]+b0, 0.f));
                    rmax[2*gnt+1] = fmaxf(rmax[2*gnt+1], fmaxf(a1[nt][3]+b1, 0.f));
                }
            }
        }

        #pragma unroll
        for (int off = 4; off <= 16; off <<= 1)
            #pragma unroll
            for (int i = 0; i < 32; ++i)
                rmax[i] = fmaxf(rmax[i], __shfl_xor_sync(0xffffffffu, rmax[i], off));

        if (lane < 4) {
            #pragma unroll
            for (int nt = 0; nt < 16; ++nt) {
                red[w*H_ + nt*8 + lane*2]     = rmax[2*nt];
                red[w*H_ + nt*8 + lane*2 + 1] = rmax[2*nt+1];
            }
        }
        __syncthreads();
        if (tid < H_) {
            float v = red[tid];
            #pragma unroll
            for (int ww = 1; ww < 8; ++ww) v = fmaxf(v, red[ww*H_ + tid]);
            v = (v < -1e8f) ? 0.f : v;
            red[tid] = v;
        }
        __syncthreads();

        if (layer == 0) {
            const __half* sWd = (const __half*)(smem + OFF_TW);
            const __half* sWb = (const __half*)(smem + OFF_TW + 32768);
            if (tid < 128) {
                const int h = tid;
                float p0 = 0.f, p1 = 0.f;
                #pragma unroll 4
                for (int c = 0; c < 128; c += 2) {
                    p0 += red[c]   * __half2float(sWd[c*128 + h]);
                    p1 += red[c+1] * __half2float(sWd[(c+1)*128 + h]);
                }
                O1[(size_t)bi*H_ + h] = p0 + p1 + bn[h];
            } else {
                const int h = tid - 128;
                float q0 = 0.f, q1 = 0.f;
                #pragma unroll 4
                for (int c = 0; c < 128; c += 2) {
                    q0 += red[c]   * __half2float(sWb[c*128 + h]);
                    q1 += red[c+1] * __half2float(sWb[(c+1)*128 + h]);
                }
                O2[(size_t)bi*H_ + h] = q0 + q1;
            }
        } else {
            const __half* sWa  = (const __half*)(smem + OFF_TW);
            const __half* sWb2 = (const __half*)(smem + OFF_TW + 65536);
            const int m = tid;
            float r0 = 0.f, r1 = 0.f, s0 = 0.f, s1 = 0.f;
            #pragma unroll 4
            for (int c = 0; c < 128; c += 2) {
                float x0 = red[c], x1 = red[c+1];
                r0 += x0 * __half2float(sWa[c*256 + m]);
                r1 += x1 * __half2float(sWa[(c+1)*256 + m]);
                s0 += x0 * __half2float(sWb2[c*256 + m]);
                s1 += x1 * __half2float(sWb2[(c+1)*256 + m]);
            }
            O1[(size_t)bi*H2_ + m] = r0 + r1;
            O2[(size_t)bi*H2_ + m] = s0 + s1 + bn[m];
        }
        __syncthreads();
        cur ^= 1;
    }
}

// ---------------------------------------------------------------------------
// pair: PIL=4 -> 256 blocks; 512 threads = 2 il-groups x 256 j, 2 il each.
// ---------------------------------------------------------------------------
#define PIL 4
#define PST 36
__global__ void __launch_bounds__(512)
pair_kernel(const float* __restrict__ R, const float* __restrict__ S,
            const float* __restrict__ outW, const float* __restrict__ outB,
            float* __restrict__ out)
{
    __shared__ float sR[V_*PST];
    __shared__ float sS[PIL*PST];
    __shared__ float sw[32];
    const int tid = threadIdx.x;
    const int j = tid & 255;
    const int ig = tid >> 8;            // il group: 0 -> il 0..1, 1 -> il 2..3
    const int b = blockIdx.y, i0 = blockIdx.x * PIL;

    float acc[2] = {0.f, 0.f};

    for (int mc = 0; mc < H2_; mc += 32) {
        __syncthreads();
        for (int idx = tid; idx < 2048; idx += 512) {
            int row = idx >> 3, c4 = idx & 7;
            float4 v = *(const float4*)(R + ((size_t)(b*V_ + row))*H2_ + mc + c4*4);
            *(float4*)&sR[row*PST + c4*4] = v;
        }
        if (tid < PIL*8) {
            int row = tid >> 3, c4 = tid & 7;
            float4 v = *(const float4*)(S + ((size_t)(b*V_ + i0 + row))*H2_ + mc + c4*4);
            *(float4*)&sS[row*PST + c4*4] = v;
        }
        if (tid < 32) sw[tid] = outW[mc + tid];
        __syncthreads();

        float rr[32], wv[32];
        #pragma unroll
        for (int k = 0; k < 8; ++k) {
            *(float4*)&rr[k*4] = *(const float4*)&sR[j*PST + k*4];
            *(float4*)&wv[k*4] = *(const float4*)&sw[k*4];
        }
        #pragma unroll
        for (int il = 0; il < 2; ++il) {
            float ss[32];
            #pragma unroll
            for (int k = 0; k < 8; ++k)
                *(float4*)&ss[k*4] = *(const float4*)&sS[(ig*2 + il)*PST + k*4];
            float a = 0.f;
            #pragma unroll
            for (int mm = 0; mm < 32; ++mm)
                a += fmaxf(rr[mm] + ss[mm], 0.f) * wv[mm];
            acc[il] += a;
        }
    }
    const float ob = outB[0];
    #pragma unroll
    for (int il = 0; il < 2; ++il) {
        float z = acc[il] + ob;
        out[((size_t)(b*V_ + i0 + ig*2 + il))*V_ + j] = 1.f / (1.f + expf(-z));
    }
}

// ---------------------------------------------------------------------------
extern "C" void kernel_launch(void* const* d_in, const int* in_sizes, int n_in,
                              void* d_out, int out_size)
{
    const int*   adj   = (const int*)  d_in[0];
    const float* x0    = (const float*)d_in[1];
    const float* e     = (const float*)d_in[2];
    const float* ec1W1 = (const float*)d_in[3];
    const float* ec1b1 = (const float*)d_in[4];
    const float* ec1W2 = (const float*)d_in[5];
    const float* ec1b2 = (const float*)d_in[6];
    const float* ec2W1 = (const float*)d_in[7];
    const float* ec2b1 = (const float*)d_in[8];
    const float* ec2W2 = (const float*)d_in[9];
    const float* ec2b2 = (const float*)d_in[10];
    const float* h3W   = (const float*)d_in[11];
    const float* h3b   = (const float*)d_in[12];
    const float* outW  = (const float*)d_in[13];
    const float* outB  = (const float*)d_in[14];
    float* out = (float*)d_out;

    float *P, *Q, *P2, *Q2, *R, *S;
    cudaGetSymbolAddress((void**)&P,  g_P);
    cudaGetSymbolAddress((void**)&Q,  g_Q);
    cudaGetSymbolAddress((void**)&P2, g_P2);
    cudaGetSymbolAddress((void**)&Q2, g_Q2);
    cudaGetSymbolAddress((void**)&R,  g_R);
    cudaGetSymbolAddress((void**)&S,  g_S);

    cudaFuncSetAttribute(ec_hmma, cudaFuncAttributeMaxDynamicSharedMemorySize, SMEM_EC1);

    int sms = 148;
    cudaDeviceGetAttribute(&sms, cudaDevAttrMultiProcessorCount, 0);
    int grid = sms < NBI ? sms : NBI;

    prep_all<<<NBI + 352 + 256, 256>>>(e, ec1W1, ec1W2, ec2W1, ec2W2, h3W,
                                       x0, ec1b1, P, Q);

    ec_hmma<<<grid, 256, SMEM_EC0>>>(P, Q, ec1b2, adj, ec2b1, P2, Q2, 0);
    ec_hmma<<<grid, 256, SMEM_EC1>>>(P2, Q2, ec2b2, adj, h3b, R, S, 1);

    dim3 pg(V_/PIL, B_);
    pair_kernel<<<pg, 512>>>(R, S, outW, outB, out);
}